// round 15
// baseline (speedup 1.0000x reference)
#include <cuda_runtime.h>
#include <math.h>
#include <stdint.h>

// Problem constants
#define Bb 128
#define Tt 400
#define Hh 512
#define H2 1024
#define Ee 128
#define Vv 50000

// Output layout (concatenated reference tuple, row-major each)
#define OFF_FINAL 0L
#define OFF_H     6400000L
#define OFF_C     6465536L
#define OFF_CT    6531072L
#define OFF_ATTN  6662144L
#define OFF_PGEN  6713344L
#define OFF_COV   6713472L

// Scratch (device globals: zero-initialized at module load; re-zeroed by the
// tail of vsoftmax_scatter_kernel so every call starts AND ends zeroed).
__device__ float g_x[Bb * Ee];
__device__ float g_decfea[Bb * H2];
__device__ float g_scores[Bb * Tt];
__device__ float g_o1[Bb * Hh];
__device__ float g_pgacc[Bb];
__device__ float g_sums[Bb];
__device__ float g_logits[(size_t)Bb * Vv];   // holds exp(logits)

__device__ __forceinline__ float tanh_fast(float x) {
    float y;
    asm("tanh.approx.f32 %0, %1;" : "=f"(y) : "f"(x));
    return y;
}
__device__ __forceinline__ float sigmoid_fast(float x) {
    return 1.0f / (1.0f + __expf(-x));
}
__device__ __forceinline__ uint32_t cvt_bf2(float2 v) {
    uint32_t r;
    asm("cvt.rn.bf16x2.f32 %0, %1, %2;" : "=r"(r) : "f"(v.y), "f"(v.x));
    return r;
}
__device__ __forceinline__ uint32_t smem_u32(const void* p) {
    return (uint32_t)__cvta_generic_to_shared(p);
}

// ---------------------------------------------------------------------------
// Small GEMM on tensor cores (tf32 m16n8k8, raw fp32 bits):
// C[128, N] (+)= [A1 | A2] @ [W1 | W2]^T + bias1 + bias2
// CTA tile 128x128, BK=16, 4-stage cp.async pipeline, K-split + atomicAdd.
// ---------------------------------------------------------------------------
#define SG_LDS 20
#define SG_STAGEF (128 * SG_LDS)
#define SG_STAGEB (SG_STAGEF * 4)
#define SG_STAGES 4
#define SG_SMEM_BYTES (SG_STAGES * SG_STAGEB * 2)   // 81920

__global__ __launch_bounds__(256) void small_gemm_mma(
    const float* __restrict__ A1, int lda1, int K1,
    const float* __restrict__ W1, int ldw1,
    const float* __restrict__ A2, int lda2, int K2,
    const float* __restrict__ W2, int ldw2,
    const int* __restrict__ a2_idx,
    const float* __restrict__ bias1, const float* __restrict__ bias2,
    float* __restrict__ C, int N, int kchunk, int split)
{
    extern __shared__ __align__(16) float sgsm[];
    float* As = sgsm;
    float* Ws = sgsm + SG_STAGES * SG_STAGEF;

    int tid = threadIdx.x;
    int lane = tid & 31;
    int wid = tid >> 5;
    int wm = (wid & 1) * 64;
    int wn = (wid >> 1) * 32;
    int bn0 = blockIdx.x * 128;
    int grp = lane >> 2;
    int qid = lane & 3;

    uint32_t sA = smem_u32(As);
    uint32_t sW = smem_u32(Ws);

    int steps_total = (K1 + K2) >> 4;
    int s0 = blockIdx.y * kchunk;
    int s1 = min(s0 + kchunk, steps_total);
    if (s0 >= steps_total) return;
    int nc = s1 - s0;

    auto prefetch = [&](int s, int stage) {
        int kk = s << 4;
        const float* Ap; int lda; int ko;
        const float* Wp; int ldw;
        bool ind = false;
        if (kk < K1) { Ap = A1; lda = lda1; ko = kk;      Wp = W1; ldw = ldw1; }
        else         { Ap = A2; lda = lda2; ko = kk - K1; Wp = W2; ldw = ldw2;
                       ind = (a2_idx != nullptr); }
#pragma unroll
        for (int i = 0; i < 2; i++) {
            int slot = i * 256 + tid;
            int row = slot >> 2;
            int c4 = (slot & 3) << 2;
            uint32_t soff = (uint32_t)(stage * SG_STAGEB + (row * SG_LDS + c4) * 4);
            size_t aoff = ind ? (size_t)a2_idx[row] * lda : (size_t)row * lda;
            asm volatile("cp.async.cg.shared.global [%0], [%1], 16;"
                         :: "r"(sA + soff), "l"(Ap + aoff + ko + c4) : "memory");
            asm volatile("cp.async.cg.shared.global [%0], [%1], 16;"
                         :: "r"(sW + soff), "l"(Wp + (size_t)(bn0 + row) * ldw + ko + c4)
                         : "memory");
        }
        asm volatile("cp.async.commit_group;" ::: "memory");
    };

    float acc[4][4][4];
#pragma unroll
    for (int i = 0; i < 4; i++)
#pragma unroll
        for (int j = 0; j < 4; j++)
#pragma unroll
            for (int r = 0; r < 4; r++) acc[i][j][r] = 0.0f;

    int committed = 0;
    for (; committed < nc && committed < 3; committed++)
        prefetch(s0 + committed, committed & 3);

    for (int s = 0; s < nc; s++) {
        if (committed < nc) { prefetch(s0 + committed, committed & 3); committed++; }
        int allow = committed - s - 1;
        if (allow <= 0)      asm volatile("cp.async.wait_group 0;" ::: "memory");
        else if (allow == 1) asm volatile("cp.async.wait_group 1;" ::: "memory");
        else if (allow == 2) asm volatile("cp.async.wait_group 2;" ::: "memory");
        else                 asm volatile("cp.async.wait_group 3;" ::: "memory");
        __syncthreads();

        const float* as = As + (s & 3) * SG_STAGEF;
        const float* ws = Ws + (s & 3) * SG_STAGEF;

#pragma unroll
        for (int k8 = 0; k8 < 2; k8++) {
            int kk = k8 * 8;
            uint32_t af[4][4];
#pragma unroll
            for (int t = 0; t < 4; t++) {
                int r0 = wm + t * 16 + grp;
                af[t][0] = __float_as_uint(as[r0 * SG_LDS + kk + qid]);
                af[t][1] = __float_as_uint(as[(r0 + 8) * SG_LDS + kk + qid]);
                af[t][2] = __float_as_uint(as[r0 * SG_LDS + kk + qid + 4]);
                af[t][3] = __float_as_uint(as[(r0 + 8) * SG_LDS + kk + qid + 4]);
            }
            uint32_t bf[4][2];
#pragma unroll
            for (int t = 0; t < 4; t++) {
                int n0 = wn + t * 8 + grp;
                bf[t][0] = __float_as_uint(ws[n0 * SG_LDS + kk + qid]);
                bf[t][1] = __float_as_uint(ws[n0 * SG_LDS + kk + qid + 4]);
            }
#pragma unroll
            for (int i = 0; i < 4; i++)
#pragma unroll
                for (int j = 0; j < 4; j++) {
                    asm volatile(
                        "mma.sync.aligned.m16n8k8.row.col.f32.tf32.tf32.f32 "
                        "{%0,%1,%2,%3}, {%4,%5,%6,%7}, {%8,%9}, {%0,%1,%2,%3};"
                        : "+f"(acc[i][j][0]), "+f"(acc[i][j][1]),
                          "+f"(acc[i][j][2]), "+f"(acc[i][j][3])
                        : "r"(af[i][0]), "r"(af[i][1]), "r"(af[i][2]), "r"(af[i][3]),
                          "r"(bf[j][0]), "r"(bf[j][1]));
                }
        }
        __syncthreads();
    }

    bool addb = (blockIdx.y == 0);
#pragma unroll
    for (int i = 0; i < 4; i++) {
        int m0 = wm + i * 16 + grp;
#pragma unroll
        for (int j = 0; j < 4; j++) {
            int n = bn0 + wn + j * 8 + 2 * qid;
            float b0 = 0.0f, b1 = 0.0f;
            if (addb) {
                if (bias1) { b0 += bias1[n]; b1 += bias1[n + 1]; }
                if (bias2) { b0 += bias2[n]; b1 += bias2[n + 1]; }
            }
            if (split) {
                atomicAdd(&C[(size_t)m0 * N + n],           acc[i][j][0] + b0);
                atomicAdd(&C[(size_t)m0 * N + n + 1],       acc[i][j][1] + b1);
                atomicAdd(&C[(size_t)(m0 + 8) * N + n],     acc[i][j][2] + b0);
                atomicAdd(&C[(size_t)(m0 + 8) * N + n + 1], acc[i][j][3] + b1);
            } else {
                C[(size_t)m0 * N + n]           = acc[i][j][0] + b0;
                C[(size_t)m0 * N + n + 1]       = acc[i][j][1] + b1;
                C[(size_t)(m0 + 8) * N + n]     = acc[i][j][2] + b0;
                C[(size_t)(m0 + 8) * N + n + 1] = acc[i][j][3] + b1;
            }
        }
    }
}

// ---------------------------------------------------------------------------
// Fused gates GEMM + LSTM cell (tf32 MMA, deep pipeline, no K-split):
// gates = x @ W_ih^T + h0 @ W_hh^T + b_ih + b_hh  (torch order i,f,g,o)
// c = sig(f)*c0 + sig(i)*tanh(g);  h = sig(o)*tanh(c)   -> out[OFF_H/OFF_C]
// Grid = 16 CTAs; CTA hb owns h-positions [hb*32, hb*32+32).
// CTA tile: M=128 (batch) x N=128 columns, column n -> gate (n>>5),
// h_local (n&31), i.e. W row (n>>5)*512 + hb*32 + (n&31).
// K = 128 (x) + 512 (h0) = 640 -> 40 BK=16 chunks, 4-stage cp.async pipeline.
// Epilogue stages the gate tile in smem, then computes the LSTM.
// ---------------------------------------------------------------------------
__global__ __launch_bounds__(256) void gates_lstm_mma(
    const float* __restrict__ x,     // [128,128]
    const float* __restrict__ Wih,   // [2048,128]
    const float* __restrict__ h0,    // [128,512]
    const float* __restrict__ Whh,   // [2048,512]
    const float* __restrict__ bih, const float* __restrict__ bhh,
    const float* __restrict__ c0,    // [128,512]
    float* __restrict__ out)
{
    extern __shared__ __align__(16) float sgsm[];
    float* As = sgsm;
    float* Ws = sgsm + SG_STAGES * SG_STAGEF;

    int tid = threadIdx.x;
    int lane = tid & 31;
    int wid = tid >> 5;
    int wm = (wid & 1) * 64;
    int wn = (wid >> 1) * 32;
    int hb = blockIdx.x;             // 0..15
    int grp = lane >> 2;
    int qid = lane & 3;

    uint32_t sA = smem_u32(As);
    uint32_t sW = smem_u32(Ws);

    const int NC = 40;               // 640 / 16

    auto prefetch = [&](int s, int stage) {
        int kk = s << 4;
        const float* Ap; int lda; int ko;
        const float* Wp; int ldw;
        if (kk < 128) { Ap = x;  lda = 128; ko = kk;       Wp = Wih; ldw = 128; }
        else          { Ap = h0; lda = 512; ko = kk - 128; Wp = Whh; ldw = 512; }
#pragma unroll
        for (int i = 0; i < 2; i++) {
            int slot = i * 256 + tid;
            int row = slot >> 2;                 // 0..127
            int c4 = (slot & 3) << 2;
            uint32_t soff = (uint32_t)(stage * SG_STAGEB + (row * SG_LDS + c4) * 4);
            asm volatile("cp.async.cg.shared.global [%0], [%1], 16;"
                         :: "r"(sA + soff), "l"(Ap + (size_t)row * lda + ko + c4)
                         : "memory");
            int wrow = (row >> 5) * 512 + hb * 32 + (row & 31);
            asm volatile("cp.async.cg.shared.global [%0], [%1], 16;"
                         :: "r"(sW + soff), "l"(Wp + (size_t)wrow * ldw + ko + c4)
                         : "memory");
        }
        asm volatile("cp.async.commit_group;" ::: "memory");
    };

    float acc[4][4][4];
#pragma unroll
    for (int i = 0; i < 4; i++)
#pragma unroll
        for (int j = 0; j < 4; j++)
#pragma unroll
            for (int r = 0; r < 4; r++) acc[i][j][r] = 0.0f;

    prefetch(0, 0); prefetch(1, 1); prefetch(2, 2);

    for (int s = 0; s < NC; s++) {
        if (s + 3 < NC) {
            prefetch(s + 3, (s + 3) & 3);
            asm volatile("cp.async.wait_group 3;" ::: "memory");
        } else if (s + 3 == NC) {
            asm volatile("cp.async.wait_group 2;" ::: "memory");
        } else if (s + 2 == NC) {
            asm volatile("cp.async.wait_group 1;" ::: "memory");
        } else {
            asm volatile("cp.async.wait_group 0;" ::: "memory");
        }
        __syncthreads();

        const float* as = As + (s & 3) * SG_STAGEF;
        const float* ws = Ws + (s & 3) * SG_STAGEF;

#pragma unroll
        for (int k8 = 0; k8 < 2; k8++) {
            int kk = k8 * 8;
            uint32_t af[4][4];
#pragma unroll
            for (int t = 0; t < 4; t++) {
                int r0 = wm + t * 16 + grp;
                af[t][0] = __float_as_uint(as[r0 * SG_LDS + kk + qid]);
                af[t][1] = __float_as_uint(as[(r0 + 8) * SG_LDS + kk + qid]);
                af[t][2] = __float_as_uint(as[r0 * SG_LDS + kk + qid + 4]);
                af[t][3] = __float_as_uint(as[(r0 + 8) * SG_LDS + kk + qid + 4]);
            }
            uint32_t bf[4][2];
#pragma unroll
            for (int t = 0; t < 4; t++) {
                int n0 = wn + t * 8 + grp;
                bf[t][0] = __float_as_uint(ws[n0 * SG_LDS + kk + qid]);
                bf[t][1] = __float_as_uint(ws[n0 * SG_LDS + kk + qid + 4]);
            }
#pragma unroll
            for (int i = 0; i < 4; i++)
#pragma unroll
                for (int j = 0; j < 4; j++) {
                    asm volatile(
                        "mma.sync.aligned.m16n8k8.row.col.f32.tf32.tf32.f32 "
                        "{%0,%1,%2,%3}, {%4,%5,%6,%7}, {%8,%9}, {%0,%1,%2,%3};"
                        : "+f"(acc[i][j][0]), "+f"(acc[i][j][1]),
                          "+f"(acc[i][j][2]), "+f"(acc[i][j][3])
                        : "r"(af[i][0]), "r"(af[i][1]), "r"(af[i][2]), "r"(af[i][3]),
                          "r"(bf[j][0]), "r"(bf[j][1]));
                }
        }
        __syncthreads();
    }

    // Stage gate tile [128 m][128 n] in smem (stride 129), then LSTM.
    float* G = sgsm;     // 128*129 = 16512 floats <= 20480 available
#pragma unroll
    for (int i = 0; i < 4; i++) {
        int m0 = wm + i * 16 + grp;
#pragma unroll
        for (int j = 0; j < 4; j++) {
            int n = wn + j * 8 + 2 * qid;
            G[m0 * 129 + n]           = acc[i][j][0];
            G[m0 * 129 + n + 1]       = acc[i][j][1];
            G[(m0 + 8) * 129 + n]     = acc[i][j][2];
            G[(m0 + 8) * 129 + n + 1] = acc[i][j][3];
        }
    }
    __syncthreads();

#pragma unroll
    for (int it = 0; it < 16; it++) {
        int e = it * 256 + tid;          // 0..4095
        int m = e >> 5;                  // 0..127
        int hl = e & 31;                 // 0..31
        int h = hb * 32 + hl;
        float gi = G[m * 129 + hl]       + bih[h]        + bhh[h];
        float gf = G[m * 129 + 32 + hl]  + bih[512 + h]  + bhh[512 + h];
        float gg = G[m * 129 + 64 + hl]  + bih[1024 + h] + bhh[1024 + h];
        float go = G[m * 129 + 96 + hl]  + bih[1536 + h] + bhh[1536 + h];
        float c = sigmoid_fast(gf) * c0[(size_t)m * Hh + h]
                + sigmoid_fast(gi) * tanhf(gg);
        float hh = sigmoid_fast(go) * tanhf(c);
        out[OFF_H + (size_t)m * Hh + h] = hh;
        out[OFF_C + (size_t)m * Hh + h] = c;
    }
}

// ---------------------------------------------------------------------------
// Vocab GEMM: bf16 m16n8k16 MMA + 4-stage cp.async fp32 pipeline.
// Writes EL = exp(o1 @ W_o2^T + b_o2) and accumulates per-row sums into
// gsums[128] (softmax is shift-invariant; logits are O(0.1), no overflow).
// ---------------------------------------------------------------------------
#define VG_LDS 24
#define VG_STAGEF (128 * VG_LDS)
#define VG_STAGEB (VG_STAGEF * 4)
#define VG_STAGES 4
#define VG_SMEM_BYTES (VG_STAGES * VG_STAGEB * 2)   // 98304

__device__ __forceinline__ void vg_prefetch(
    int s, int stage, const float* __restrict__ A, const float* __restrict__ W,
    int bn0, uint32_t sA, uint32_t sW)
{
    int ck = s * 16;
    int tid = threadIdx.x;
#pragma unroll
    for (int i = 0; i < 2; i++) {
        int slot = i * 256 + tid;
        int row = slot >> 2;
        int c4 = (slot & 3) << 2;
        uint32_t soff = (uint32_t)(stage * VG_STAGEB + (row * VG_LDS + c4) * 4);
        asm volatile("cp.async.cg.shared.global [%0], [%1], 16;"
                     :: "r"(sA + soff), "l"(A + row * 512 + ck + c4) : "memory");
        int nrow = bn0 + row;
        if (nrow < Vv)
            asm volatile("cp.async.cg.shared.global [%0], [%1], 16;"
                         :: "r"(sW + soff), "l"(W + (size_t)nrow * 512 + ck + c4) : "memory");
    }
    asm volatile("cp.async.commit_group;" ::: "memory");
}

__global__ __launch_bounds__(256) void vocab_gemm_mma(
    const float* __restrict__ A, const float* __restrict__ W,
    const float* __restrict__ bias, float* __restrict__ EL,
    float* __restrict__ gsums)
{
    extern __shared__ __align__(16) float vgsm[];
    float* As = vgsm;
    float* Ws = vgsm + VG_STAGES * VG_STAGEF;

    int tid = threadIdx.x;
    int lane = tid & 31;
    int wid = tid >> 5;
    int wm = (wid & 1) * 64;
    int wn = (wid >> 1) * 32;
    int bn0 = blockIdx.x * 128;

    int grp = lane >> 2;
    int qid = lane & 3;

    uint32_t sA = smem_u32(As);
    uint32_t sW = smem_u32(Ws);

    if (bn0 + 128 > Vv) {
#pragma unroll
        for (int st = 0; st < VG_STAGES; st++)
            for (int slot = tid; slot < 512; slot += 256) {
                int row = slot >> 2;
                int c4 = (slot & 3) << 2;
                if (bn0 + row >= Vv)
                    *(float4*)&Ws[st * VG_STAGEF + row * VG_LDS + c4] =
                        make_float4(0.f, 0.f, 0.f, 0.f);
            }
        __syncthreads();
    }

    float acc[4][4][4];
#pragma unroll
    for (int i = 0; i < 4; i++)
#pragma unroll
        for (int j = 0; j < 4; j++)
#pragma unroll
            for (int r = 0; r < 4; r++) acc[i][j][r] = 0.0f;

    vg_prefetch(0, 0, A, W, bn0, sA, sW);
    vg_prefetch(1, 1, A, W, bn0, sA, sW);
    vg_prefetch(2, 2, A, W, bn0, sA, sW);

    for (int s = 0; s < 32; s++) {
        int stage = s & 3;
        if (s < 29) {
            vg_prefetch(s + 3, (s + 3) & 3, A, W, bn0, sA, sW);
            asm volatile("cp.async.wait_group 3;" ::: "memory");
        } else if (s == 29) {
            asm volatile("cp.async.wait_group 2;" ::: "memory");
        } else if (s == 30) {
            asm volatile("cp.async.wait_group 1;" ::: "memory");
        } else {
            asm volatile("cp.async.wait_group 0;" ::: "memory");
        }
        __syncthreads();

        const float* as = As + stage * VG_STAGEF;
        const float* ws = Ws + stage * VG_STAGEF;

        uint32_t af[4][4];
#pragma unroll
        for (int t = 0; t < 4; t++) {
            int r0 = wm + t * 16 + grp;
            const float* b0 = as + r0 * VG_LDS;
            const float* b1 = as + (r0 + 8) * VG_LDS;
            af[t][0] = cvt_bf2(*(const float2*)(b0 + 2 * qid));
            af[t][1] = cvt_bf2(*(const float2*)(b1 + 2 * qid));
            af[t][2] = cvt_bf2(*(const float2*)(b0 + 8 + 2 * qid));
            af[t][3] = cvt_bf2(*(const float2*)(b1 + 8 + 2 * qid));
        }
        uint32_t bf[4][2];
#pragma unroll
        for (int t = 0; t < 4; t++) {
            int n0 = wn + t * 8 + grp;
            const float* b = ws + n0 * VG_LDS;
            bf[t][0] = cvt_bf2(*(const float2*)(b + 2 * qid));
            bf[t][1] = cvt_bf2(*(const float2*)(b + 8 + 2 * qid));
        }
#pragma unroll
        for (int i = 0; i < 4; i++)
#pragma unroll
            for (int j = 0; j < 4; j++) {
                asm volatile(
                    "mma.sync.aligned.m16n8k16.row.col.f32.bf16.bf16.f32 "
                    "{%0,%1,%2,%3}, {%4,%5,%6,%7}, {%8,%9}, {%0,%1,%2,%3};"
                    : "+f"(acc[i][j][0]), "+f"(acc[i][j][1]),
                      "+f"(acc[i][j][2]), "+f"(acc[i][j][3])
                    : "r"(af[i][0]), "r"(af[i][1]), "r"(af[i][2]), "r"(af[i][3]),
                      "r"(bf[j][0]), "r"(bf[j][1]));
            }
        __syncthreads();
    }

    // Epilogue: exp(logit) store + per-row sum reduction.
    float* rowsums = vgsm;
    if (tid < 128) rowsums[tid] = 0.0f;
    __syncthreads();

#pragma unroll
    for (int i = 0; i < 4; i++) {
        int m0 = wm + i * 16 + grp;
        float rsA = 0.0f, rsB = 0.0f;
#pragma unroll
        for (int j = 0; j < 4; j++) {
            int n = bn0 + wn + j * 8 + 2 * qid;
            if (n < Vv) {
                float2 b2 = *(const float2*)&bias[n];
                float e0 = __expf(acc[i][j][0] + b2.x);
                float e1 = __expf(acc[i][j][1] + b2.y);
                float e2 = __expf(acc[i][j][2] + b2.x);
                float e3 = __expf(acc[i][j][3] + b2.y);
                *(float2*)&EL[(size_t)m0 * Vv + n]       = make_float2(e0, e1);
                *(float2*)&EL[(size_t)(m0 + 8) * Vv + n] = make_float2(e2, e3);
                rsA += e0 + e1;
                rsB += e2 + e3;
            }
        }
        rsA += __shfl_down_sync(0xffffffffu, rsA, 2);
        rsA += __shfl_down_sync(0xffffffffu, rsA, 1);
        rsB += __shfl_down_sync(0xffffffffu, rsB, 2);
        rsB += __shfl_down_sync(0xffffffffu, rsB, 1);
        if (qid == 0) {
            atomicAdd(&rowsums[m0], rsA);
            atomicAdd(&rowsums[m0 + 8], rsB);
        }
    }
    __syncthreads();
    if (tid < 128) atomicAdd(&gsums[tid], rowsums[tid]);
}

// ---------------------------------------------------------------------------
// Attention scores
// ---------------------------------------------------------------------------
__global__ __launch_bounds__(256) void scores_kernel(
    const float* __restrict__ ef, const float* __restrict__ dec,
    const float* __restrict__ vw, const float* __restrict__ Wc,
    const float* __restrict__ cov, float* __restrict__ scores)
{
    __shared__ __align__(16) float s_dec[H2];
    __shared__ __align__(16) float s_v[H2];
    __shared__ __align__(16) float s_wc[H2];
    int b = blockIdx.y;
    int tid = threadIdx.x;
    for (int i = tid; i < H2; i += 256) {
        s_dec[i] = dec[(size_t)b * H2 + i];
        s_v[i] = vw[i];
        s_wc[i] = Wc[i];
    }
    __syncthreads();

    int warp = tid >> 5, lane = tid & 31;
    int t = blockIdx.x * 8 + warp;
    float cv = cov[(size_t)b * Tt + t];
    const float* p = ef + ((size_t)b * Tt + t) * H2;

    float acc = 0.0f;
#pragma unroll
    for (int i = 0; i < 8; i++) {
        int n = i * 128 + lane * 4;
        float4 e4 = *(const float4*)(p + n);
        acc += tanh_fast(e4.x + s_dec[n]     + cv * s_wc[n])     * s_v[n];
        acc += tanh_fast(e4.y + s_dec[n + 1] + cv * s_wc[n + 1]) * s_v[n + 1];
        acc += tanh_fast(e4.z + s_dec[n + 2] + cv * s_wc[n + 2]) * s_v[n + 2];
        acc += tanh_fast(e4.w + s_dec[n + 3] + cv * s_wc[n + 3]) * s_v[n + 3];
    }
#pragma unroll
    for (int o = 16; o > 0; o >>= 1) acc += __shfl_down_sync(0xffffffffu, acc, o);
    if (lane == 0) scores[(size_t)b * Tt + t] = acc;
}

// ---------------------------------------------------------------------------
// Fused attention: softmax over T (+mask renorm +coverage), half of c_t,
// partial p_gen dot (atomicAdd into g_pgacc). grid (2,128), 512 threads.
// ---------------------------------------------------------------------------
__global__ __launch_bounds__(512) void attn_fused_kernel(
    const float* __restrict__ scores, const float* __restrict__ mask,
    const float* __restrict__ cov, const float* __restrict__ eo,
    const float* __restrict__ x, const float* __restrict__ Wpg,
    float* __restrict__ pgacc, float* __restrict__ out)
{
    __shared__ float red[512];
    __shared__ float sa[Tt];

    int b = blockIdx.y, hx = blockIdx.x, tid = threadIdx.x;

    float s = (tid < Tt) ? scores[(size_t)b * Tt + tid] : -1e30f;
    red[tid] = s; __syncthreads();
    for (int st = 256; st > 0; st >>= 1) {
        if (tid < st) red[tid] = fmaxf(red[tid], red[tid + st]);
        __syncthreads();
    }
    float m = red[0]; __syncthreads();

    float e = (tid < Tt) ? __expf(s - m) : 0.0f;
    red[tid] = e; __syncthreads();
    for (int st = 256; st > 0; st >>= 1) {
        if (tid < st) red[tid] += red[tid + st];
        __syncthreads();
    }
    float S = red[0]; __syncthreads();

    float a = (tid < Tt) ? (e / S) * mask[(size_t)b * Tt + tid] : 0.0f;
    red[tid] = a; __syncthreads();
    for (int st = 256; st > 0; st >>= 1) {
        if (tid < st) red[tid] += red[tid + st];
        __syncthreads();
    }
    float S2 = red[0] + 1e-12f;

    float attn = a / S2;
    if (tid < Tt) {
        sa[tid] = attn;
        if (hx == 0) {
            out[OFF_ATTN + (size_t)b * Tt + tid] = attn;
            out[OFF_COV  + (size_t)b * Tt + tid] = cov[(size_t)b * Tt + tid] + attn;
        }
    }
    __syncthreads();

    int n = hx * 512 + tid;
    const float* p = eo + (size_t)b * Tt * H2 + n;
    float acc = 0.0f;
#pragma unroll 16
    for (int t = 0; t < Tt; t++) acc += sa[t] * p[(size_t)t * H2];
    out[OFF_CT + (size_t)b * H2 + n] = acc;

    float pacc = acc * Wpg[n];
    if (hx == 0) {
        pacc += out[OFF_H + (size_t)b * Hh + tid] * Wpg[1024 + tid];
        if (tid < Ee) pacc += x[(size_t)b * Ee + tid] * Wpg[2048 + tid];
    } else {
        pacc += out[OFF_C + (size_t)b * Hh + tid] * Wpg[1536 + tid];
    }
    red[tid] = pacc; __syncthreads();
    for (int st = 256; st > 0; st >>= 1) {
        if (tid < st) red[tid] += red[tid + st];
        __syncthreads();
    }
    if (tid == 0) atomicAdd(&pgacc[b], red[0]);
}

// ---------------------------------------------------------------------------
// Final: F = expL * pg / S (single pass) + p_gen finalize + pointer scatter
// + scratch re-zero. grid = 128, 1024 threads.
// All threads read gpg/gsums BEFORE thread 0 zeroes them (barrier-ordered).
// ---------------------------------------------------------------------------
__global__ __launch_bounds__(1024) void vsoftmax_scatter_kernel(
    const float* __restrict__ expL, const int* __restrict__ ebev,
    const float* __restrict__ bpg,
    float* __restrict__ gx, float* __restrict__ gdec, float* __restrict__ go1,
    float* __restrict__ gpg, float* __restrict__ gsums,
    float* __restrict__ out)
{
    int b = blockIdx.x, tid = threadIdx.x;

    float pgacc_v = gpg[b];
    float S = gsums[b];
    __syncthreads();
    if (tid == 0) {
        gpg[b] = 0.0f;
        gsums[b] = 0.0f;
    }

    float pg = sigmoid_fast(pgacc_v + bpg[0]);
    if (tid == 0) out[OFF_PGEN + b] = pg;

    float scale = pg / S;
    const float4* L4 = (const float4*)(expL + (size_t)b * Vv);
    float4* F4 = (float4*)(out + (size_t)b * Vv);
    for (int j = tid; j < Vv / 4; j += 1024) {
        float4 v = L4[j];
        F4[j] = make_float4(v.x * scale, v.y * scale, v.z * scale, v.w * scale);
    }
    __syncthreads();

    if (tid < Tt) {
        float a = out[OFF_ATTN + (size_t)b * Tt + tid];
        atomicAdd(&out[(size_t)b * Vv + ebev[(size_t)b * Tt + tid]], (1.0f - pg) * a);
    }

    // re-zero split-GEMM accumulators for the next call
    int gi = b * 1024 + tid;
    int gs = 128 * 1024;
    for (int j = gi; j < Bb * Ee; j += gs) gx[j] = 0.0f;
    for (int j = gi; j < Bb * H2; j += gs) gdec[j] = 0.0f;
    for (int j = gi; j < Bb * Hh; j += gs) go1[j] = 0.0f;
}

// ---------------------------------------------------------------------------
// Host launch
// ---------------------------------------------------------------------------
static void launch_small(const float* A1, int lda1, int K1, const float* W1, int ldw1,
                         const float* A2, int lda2, int K2, const float* W2, int ldw2,
                         const int* a2_idx,
                         const float* b1, const float* b2, float* C, int N, int kchunk)
{
    int steps = (K1 + K2) >> 4;
    int ky = (steps + kchunk - 1) / kchunk;
    dim3 grid(N / 128, ky);
    small_gemm_mma<<<grid, 256, SG_SMEM_BYTES>>>(
        A1, lda1, K1, W1, ldw1, A2, lda2, K2, W2, ldw2,
        a2_idx, b1, b2, C, N, kchunk, (ky > 1) ? 1 : 0);
}

extern "C" void kernel_launch(void* const* d_in, const int* in_sizes, int n_in,
                              void* d_out_v, int out_size)
{
    (void)in_sizes; (void)n_in; (void)out_size;
    const int*   y    = (const int*)  d_in[0];
    const float* h0   = (const float*)d_in[1];
    const float* c0   = (const float*)d_in[2];
    const float* ct1  = (const float*)d_in[3];
    const float* eo   = (const float*)d_in[4];
    const float* ef   = (const float*)d_in[5];
    const float* mask = (const float*)d_in[6];
    const int*   ebev = (const int*)  d_in[7];
    const float* cov  = (const float*)d_in[8];
    const float* emb  = (const float*)d_in[9];
    const float* W_c  = (const float*)d_in[10];
    const float* W_dp = (const float*)d_in[11];
    const float* b_dp = (const float*)d_in[12];
    const float* v_w  = (const float*)d_in[13];
    const float* W_xc = (const float*)d_in[14];
    const float* b_xc = (const float*)d_in[15];
    const float* W_ih = (const float*)d_in[16];
    const float* W_hh = (const float*)d_in[17];
    const float* b_ih = (const float*)d_in[18];
    const float* b_hh = (const float*)d_in[19];
    const float* W_pg = (const float*)d_in[20];
    const float* b_pg = (const float*)d_in[21];
    const float* W_o1 = (const float*)d_in[22];
    const float* b_o1 = (const float*)d_in[23];
    const float* W_o2 = (const float*)d_in[24];
    const float* b_o2 = (const float*)d_in[25];
    float* out = (float*)d_out_v;

    float *p_x, *p_dec, *p_scores, *p_o1, *p_logits, *p_pgacc, *p_sums;
    cudaGetSymbolAddress((void**)&p_x,      g_x);
    cudaGetSymbolAddress((void**)&p_dec,    g_decfea);
    cudaGetSymbolAddress((void**)&p_scores, g_scores);
    cudaGetSymbolAddress((void**)&p_o1,     g_o1);
    cudaGetSymbolAddress((void**)&p_logits, g_logits);
    cudaGetSymbolAddress((void**)&p_pgacc,  g_pgacc);
    cudaGetSymbolAddress((void**)&p_sums,   g_sums);

    cudaFuncSetAttribute(vocab_gemm_mma, cudaFuncAttributeMaxDynamicSharedMemorySize,
                         VG_SMEM_BYTES);
    cudaFuncSetAttribute(small_gemm_mma, cudaFuncAttributeMaxDynamicSharedMemorySize,
                         SG_SMEM_BYTES);
    cudaFuncSetAttribute(gates_lstm_mma, cudaFuncAttributeMaxDynamicSharedMemorySize,
                         SG_SMEM_BYTES);

    // Accumulators are zero here (module-load init + re-zero in final kernel).

    // 1. x = [c_t_1 | emb[y]] @ W_xc^T + b_xc  (grid (1,12), nc=6)
    launch_small(ct1, H2, H2, W_xc, 1152,
                 emb, Ee, Ee, W_xc + 1024, 1152, y,
                 b_xc, nullptr, p_x, Ee, 6);

    // 2+3. fused gates GEMM + LSTM cell (16 CTAs, nc=40, no split)
    gates_lstm_mma<<<16, 256, SG_SMEM_BYTES>>>(p_x, W_ih, h0, W_hh,
                                               b_ih, b_hh, c0, out);

    // 4. dec_fea = [h | c] @ W_dp^T + b_dp  (grid (8,8), nc=8)
    launch_small(out + OFF_H, Hh, Hh, W_dp, H2,
                 out + OFF_C, Hh, Hh, W_dp + 512, H2, nullptr,
                 b_dp, nullptr, p_dec, H2, 8);

    // 5. attention scores
    scores_kernel<<<dim3(Tt / 8, Bb), 256>>>(ef, p_dec, v_w, W_c, cov, p_scores);

    // 6. fused softmax + c_t halves + partial p_gen
    attn_fused_kernel<<<dim3(2, Bb), 512>>>(p_scores, mask, cov, eo, p_x, W_pg,
                                            p_pgacc, out);

    // 7. o1 = [h | c_t] @ W_o1^T + b_o1  (grid (4,12), nc=8)
    launch_small(out + OFF_H, Hh, Hh, W_o1, 3 * Hh,
                 out + OFF_CT, H2, H2, W_o1 + 512, 3 * Hh, nullptr,
                 b_o1, nullptr, p_o1, Hh, 8);

    // 8. exp(logits) + row sums via bf16 MMA GEMM
    vocab_gemm_mma<<<(Vv + 127) / 128, 256, VG_SMEM_BYTES>>>(p_o1, W_o2, b_o2,
                                                             p_logits, p_sums);

    // 9. final: scale expL by pg/S + scatter + re-zero
    vsoftmax_scatter_kernel<<<Bb, 1024>>>(p_logits, ebev, b_pg,
                                          p_x, p_dec, p_o1,
                                          p_pgacc, p_sums, out);
}

// round 16
// speedup vs baseline: 1.1699x; 1.1699x over previous
#include <cuda_runtime.h>
#include <math.h>
#include <stdint.h>

// Problem constants
#define Bb 128
#define Tt 400
#define Hh 512
#define H2 1024
#define Ee 128
#define Vv 50000

// Output layout (concatenated reference tuple, row-major each)
#define OFF_FINAL 0L
#define OFF_H     6400000L
#define OFF_C     6465536L
#define OFF_CT    6531072L
#define OFF_ATTN  6662144L
#define OFF_PGEN  6713344L
#define OFF_COV   6713472L

// Scratch (device globals: zero-initialized at module load; re-zeroed by the
// tail of vsoftmax_scatter_kernel so every call starts AND ends zeroed).
__device__ float g_x[Bb * Ee];
__device__ float g_gates[Bb * 4 * Hh];
__device__ float g_decfea[Bb * H2];
__device__ float g_scores[Bb * Tt];
__device__ float g_o1[Bb * Hh];
__device__ float g_pgacc[Bb];
__device__ float g_sums[Bb];
__device__ float g_logits[(size_t)Bb * Vv];   // holds exp(logits)

__device__ __forceinline__ float tanh_fast(float x) {
    float y;
    asm("tanh.approx.f32 %0, %1;" : "=f"(y) : "f"(x));
    return y;
}
__device__ __forceinline__ float sigmoid_fast(float x) {
    return 1.0f / (1.0f + __expf(-x));
}
__device__ __forceinline__ uint32_t cvt_bf2(float2 v) {
    uint32_t r;
    asm("cvt.rn.bf16x2.f32 %0, %1, %2;" : "=r"(r) : "f"(v.y), "f"(v.x));
    return r;
}
__device__ __forceinline__ uint32_t smem_u32(const void* p) {
    return (uint32_t)__cvta_generic_to_shared(p);
}

// ---------------------------------------------------------------------------
// Small GEMM on tensor cores (tf32 m16n8k8, raw fp32 bits):
// C[128, N] (+)= [A1 | A2] @ [W1 | W2]^T + bias1 + bias2
// CTA tile 128x128, BK=16, 4-stage cp.async pipeline, K-split + atomicAdd.
// ---------------------------------------------------------------------------
#define SG_LDS 20
#define SG_STAGEF (128 * SG_LDS)
#define SG_STAGEB (SG_STAGEF * 4)
#define SG_STAGES 4
#define SG_SMEM_BYTES (SG_STAGES * SG_STAGEB * 2)   // 81920

__global__ __launch_bounds__(256) void small_gemm_mma(
    const float* __restrict__ A1, int lda1, int K1,
    const float* __restrict__ W1, int ldw1,
    const float* __restrict__ A2, int lda2, int K2,
    const float* __restrict__ W2, int ldw2,
    const int* __restrict__ a2_idx,
    const float* __restrict__ bias1, const float* __restrict__ bias2,
    float* __restrict__ C, int N, int kchunk, int split)
{
    extern __shared__ __align__(16) float sgsm[];
    float* As = sgsm;
    float* Ws = sgsm + SG_STAGES * SG_STAGEF;

    int tid = threadIdx.x;
    int lane = tid & 31;
    int wid = tid >> 5;
    int wm = (wid & 1) * 64;
    int wn = (wid >> 1) * 32;
    int bn0 = blockIdx.x * 128;
    int grp = lane >> 2;
    int qid = lane & 3;

    uint32_t sA = smem_u32(As);
    uint32_t sW = smem_u32(Ws);

    int steps_total = (K1 + K2) >> 4;
    int s0 = blockIdx.y * kchunk;
    int s1 = min(s0 + kchunk, steps_total);
    if (s0 >= steps_total) return;
    int nc = s1 - s0;

    auto prefetch = [&](int s, int stage) {
        int kk = s << 4;
        const float* Ap; int lda; int ko;
        const float* Wp; int ldw;
        bool ind = false;
        if (kk < K1) { Ap = A1; lda = lda1; ko = kk;      Wp = W1; ldw = ldw1; }
        else         { Ap = A2; lda = lda2; ko = kk - K1; Wp = W2; ldw = ldw2;
                       ind = (a2_idx != nullptr); }
#pragma unroll
        for (int i = 0; i < 2; i++) {
            int slot = i * 256 + tid;
            int row = slot >> 2;
            int c4 = (slot & 3) << 2;
            uint32_t soff = (uint32_t)(stage * SG_STAGEB + (row * SG_LDS + c4) * 4);
            size_t aoff = ind ? (size_t)a2_idx[row] * lda : (size_t)row * lda;
            asm volatile("cp.async.cg.shared.global [%0], [%1], 16;"
                         :: "r"(sA + soff), "l"(Ap + aoff + ko + c4) : "memory");
            asm volatile("cp.async.cg.shared.global [%0], [%1], 16;"
                         :: "r"(sW + soff), "l"(Wp + (size_t)(bn0 + row) * ldw + ko + c4)
                         : "memory");
        }
        asm volatile("cp.async.commit_group;" ::: "memory");
    };

    float acc[4][4][4];
#pragma unroll
    for (int i = 0; i < 4; i++)
#pragma unroll
        for (int j = 0; j < 4; j++)
#pragma unroll
            for (int r = 0; r < 4; r++) acc[i][j][r] = 0.0f;

    int committed = 0;
    for (; committed < nc && committed < 3; committed++)
        prefetch(s0 + committed, committed & 3);

    for (int s = 0; s < nc; s++) {
        if (committed < nc) { prefetch(s0 + committed, committed & 3); committed++; }
        int allow = committed - s - 1;
        if (allow <= 0)      asm volatile("cp.async.wait_group 0;" ::: "memory");
        else if (allow == 1) asm volatile("cp.async.wait_group 1;" ::: "memory");
        else if (allow == 2) asm volatile("cp.async.wait_group 2;" ::: "memory");
        else                 asm volatile("cp.async.wait_group 3;" ::: "memory");
        __syncthreads();

        const float* as = As + (s & 3) * SG_STAGEF;
        const float* ws = Ws + (s & 3) * SG_STAGEF;

#pragma unroll
        for (int k8 = 0; k8 < 2; k8++) {
            int kk = k8 * 8;
            uint32_t af[4][4];
#pragma unroll
            for (int t = 0; t < 4; t++) {
                int r0 = wm + t * 16 + grp;
                af[t][0] = __float_as_uint(as[r0 * SG_LDS + kk + qid]);
                af[t][1] = __float_as_uint(as[(r0 + 8) * SG_LDS + kk + qid]);
                af[t][2] = __float_as_uint(as[r0 * SG_LDS + kk + qid + 4]);
                af[t][3] = __float_as_uint(as[(r0 + 8) * SG_LDS + kk + qid + 4]);
            }
            uint32_t bf[4][2];
#pragma unroll
            for (int t = 0; t < 4; t++) {
                int n0 = wn + t * 8 + grp;
                bf[t][0] = __float_as_uint(ws[n0 * SG_LDS + kk + qid]);
                bf[t][1] = __float_as_uint(ws[n0 * SG_LDS + kk + qid + 4]);
            }
#pragma unroll
            for (int i = 0; i < 4; i++)
#pragma unroll
                for (int j = 0; j < 4; j++) {
                    asm volatile(
                        "mma.sync.aligned.m16n8k8.row.col.f32.tf32.tf32.f32 "
                        "{%0,%1,%2,%3}, {%4,%5,%6,%7}, {%8,%9}, {%0,%1,%2,%3};"
                        : "+f"(acc[i][j][0]), "+f"(acc[i][j][1]),
                          "+f"(acc[i][j][2]), "+f"(acc[i][j][3])
                        : "r"(af[i][0]), "r"(af[i][1]), "r"(af[i][2]), "r"(af[i][3]),
                          "r"(bf[j][0]), "r"(bf[j][1]));
                }
        }
        __syncthreads();
    }

    bool addb = (blockIdx.y == 0);
#pragma unroll
    for (int i = 0; i < 4; i++) {
        int m0 = wm + i * 16 + grp;
#pragma unroll
        for (int j = 0; j < 4; j++) {
            int n = bn0 + wn + j * 8 + 2 * qid;
            float b0 = 0.0f, b1 = 0.0f;
            if (addb) {
                if (bias1) { b0 += bias1[n]; b1 += bias1[n + 1]; }
                if (bias2) { b0 += bias2[n]; b1 += bias2[n + 1]; }
            }
            if (split) {
                atomicAdd(&C[(size_t)m0 * N + n],           acc[i][j][0] + b0);
                atomicAdd(&C[(size_t)m0 * N + n + 1],       acc[i][j][1] + b1);
                atomicAdd(&C[(size_t)(m0 + 8) * N + n],     acc[i][j][2] + b0);
                atomicAdd(&C[(size_t)(m0 + 8) * N + n + 1], acc[i][j][3] + b1);
            } else {
                C[(size_t)m0 * N + n]           = acc[i][j][0] + b0;
                C[(size_t)m0 * N + n + 1]       = acc[i][j][1] + b1;
                C[(size_t)(m0 + 8) * N + n]     = acc[i][j][2] + b0;
                C[(size_t)(m0 + 8) * N + n + 1] = acc[i][j][3] + b1;
            }
        }
    }
}

// ---------------------------------------------------------------------------
// Vocab GEMM: bf16 m16n8k16 MMA + 4-stage cp.async fp32 pipeline.
// Writes EL = exp(o1 @ W_o2^T + b_o2) and accumulates per-row sums into
// gsums[128] (softmax is shift-invariant; logits are O(0.1), no overflow).
// ---------------------------------------------------------------------------
#define VG_LDS 24
#define VG_STAGEF (128 * VG_LDS)
#define VG_STAGEB (VG_STAGEF * 4)
#define VG_STAGES 4
#define VG_SMEM_BYTES (VG_STAGES * VG_STAGEB * 2)   // 98304

__device__ __forceinline__ void vg_prefetch(
    int s, int stage, const float* __restrict__ A, const float* __restrict__ W,
    int bn0, uint32_t sA, uint32_t sW)
{
    int ck = s * 16;
    int tid = threadIdx.x;
#pragma unroll
    for (int i = 0; i < 2; i++) {
        int slot = i * 256 + tid;
        int row = slot >> 2;
        int c4 = (slot & 3) << 2;
        uint32_t soff = (uint32_t)(stage * VG_STAGEB + (row * VG_LDS + c4) * 4);
        asm volatile("cp.async.cg.shared.global [%0], [%1], 16;"
                     :: "r"(sA + soff), "l"(A + row * 512 + ck + c4) : "memory");
        int nrow = bn0 + row;
        if (nrow < Vv)
            asm volatile("cp.async.cg.shared.global [%0], [%1], 16;"
                         :: "r"(sW + soff), "l"(W + (size_t)nrow * 512 + ck + c4) : "memory");
    }
    asm volatile("cp.async.commit_group;" ::: "memory");
}

__global__ __launch_bounds__(256) void vocab_gemm_mma(
    const float* __restrict__ A, const float* __restrict__ W,
    const float* __restrict__ bias, float* __restrict__ EL,
    float* __restrict__ gsums)
{
    extern __shared__ __align__(16) float vgsm[];
    float* As = vgsm;
    float* Ws = vgsm + VG_STAGES * VG_STAGEF;

    int tid = threadIdx.x;
    int lane = tid & 31;
    int wid = tid >> 5;
    int wm = (wid & 1) * 64;
    int wn = (wid >> 1) * 32;
    int bn0 = blockIdx.x * 128;

    int grp = lane >> 2;
    int qid = lane & 3;

    uint32_t sA = smem_u32(As);
    uint32_t sW = smem_u32(Ws);

    if (bn0 + 128 > Vv) {
#pragma unroll
        for (int st = 0; st < VG_STAGES; st++)
            for (int slot = tid; slot < 512; slot += 256) {
                int row = slot >> 2;
                int c4 = (slot & 3) << 2;
                if (bn0 + row >= Vv)
                    *(float4*)&Ws[st * VG_STAGEF + row * VG_LDS + c4] =
                        make_float4(0.f, 0.f, 0.f, 0.f);
            }
        __syncthreads();
    }

    float acc[4][4][4];
#pragma unroll
    for (int i = 0; i < 4; i++)
#pragma unroll
        for (int j = 0; j < 4; j++)
#pragma unroll
            for (int r = 0; r < 4; r++) acc[i][j][r] = 0.0f;

    vg_prefetch(0, 0, A, W, bn0, sA, sW);
    vg_prefetch(1, 1, A, W, bn0, sA, sW);
    vg_prefetch(2, 2, A, W, bn0, sA, sW);

    for (int s = 0; s < 32; s++) {
        int stage = s & 3;
        if (s < 29) {
            vg_prefetch(s + 3, (s + 3) & 3, A, W, bn0, sA, sW);
            asm volatile("cp.async.wait_group 3;" ::: "memory");
        } else if (s == 29) {
            asm volatile("cp.async.wait_group 2;" ::: "memory");
        } else if (s == 30) {
            asm volatile("cp.async.wait_group 1;" ::: "memory");
        } else {
            asm volatile("cp.async.wait_group 0;" ::: "memory");
        }
        __syncthreads();

        const float* as = As + stage * VG_STAGEF;
        const float* ws = Ws + stage * VG_STAGEF;

        uint32_t af[4][4];
#pragma unroll
        for (int t = 0; t < 4; t++) {
            int r0 = wm + t * 16 + grp;
            const float* b0 = as + r0 * VG_LDS;
            const float* b1 = as + (r0 + 8) * VG_LDS;
            af[t][0] = cvt_bf2(*(const float2*)(b0 + 2 * qid));
            af[t][1] = cvt_bf2(*(const float2*)(b1 + 2 * qid));
            af[t][2] = cvt_bf2(*(const float2*)(b0 + 8 + 2 * qid));
            af[t][3] = cvt_bf2(*(const float2*)(b1 + 8 + 2 * qid));
        }
        uint32_t bf[4][2];
#pragma unroll
        for (int t = 0; t < 4; t++) {
            int n0 = wn + t * 8 + grp;
            const float* b = ws + n0 * VG_LDS;
            bf[t][0] = cvt_bf2(*(const float2*)(b + 2 * qid));
            bf[t][1] = cvt_bf2(*(const float2*)(b + 8 + 2 * qid));
        }
#pragma unroll
        for (int i = 0; i < 4; i++)
#pragma unroll
            for (int j = 0; j < 4; j++) {
                asm volatile(
                    "mma.sync.aligned.m16n8k16.row.col.f32.bf16.bf16.f32 "
                    "{%0,%1,%2,%3}, {%4,%5,%6,%7}, {%8,%9}, {%0,%1,%2,%3};"
                    : "+f"(acc[i][j][0]), "+f"(acc[i][j][1]),
                      "+f"(acc[i][j][2]), "+f"(acc[i][j][3])
                    : "r"(af[i][0]), "r"(af[i][1]), "r"(af[i][2]), "r"(af[i][3]),
                      "r"(bf[j][0]), "r"(bf[j][1]));
            }
        __syncthreads();
    }

    // Epilogue: exp(logit) store + per-row sum reduction.
    float* rowsums = vgsm;
    if (tid < 128) rowsums[tid] = 0.0f;
    __syncthreads();

#pragma unroll
    for (int i = 0; i < 4; i++) {
        int m0 = wm + i * 16 + grp;
        float rsA = 0.0f, rsB = 0.0f;
#pragma unroll
        for (int j = 0; j < 4; j++) {
            int n = bn0 + wn + j * 8 + 2 * qid;
            if (n < Vv) {
                float2 b2 = *(const float2*)&bias[n];
                float e0 = __expf(acc[i][j][0] + b2.x);
                float e1 = __expf(acc[i][j][1] + b2.y);
                float e2 = __expf(acc[i][j][2] + b2.x);
                float e3 = __expf(acc[i][j][3] + b2.y);
                *(float2*)&EL[(size_t)m0 * Vv + n]       = make_float2(e0, e1);
                *(float2*)&EL[(size_t)(m0 + 8) * Vv + n] = make_float2(e2, e3);
                rsA += e0 + e1;
                rsB += e2 + e3;
            }
        }
        rsA += __shfl_down_sync(0xffffffffu, rsA, 2);
        rsA += __shfl_down_sync(0xffffffffu, rsA, 1);
        rsB += __shfl_down_sync(0xffffffffu, rsB, 2);
        rsB += __shfl_down_sync(0xffffffffu, rsB, 1);
        if (qid == 0) {
            atomicAdd(&rowsums[m0], rsA);
            atomicAdd(&rowsums[m0 + 8], rsB);
        }
    }
    __syncthreads();
    if (tid < 128) atomicAdd(&gsums[tid], rowsums[tid]);
}

// ---------------------------------------------------------------------------
// LSTM elementwise (float4 vectorized)
// ---------------------------------------------------------------------------
__global__ void lstm_kernel(const float* __restrict__ gates, const float* __restrict__ c0,
                            float* __restrict__ out) {
    int q = blockIdx.x * blockDim.x + threadIdx.x;
    if (q >= Bb * Hh / 4) return;
    int b = q >> 7;
    int h4 = (q & 127) << 2;
    const float* g = gates + (size_t)b * 4 * Hh;
    float4 gi = *(const float4*)&g[h4];
    float4 gf = *(const float4*)&g[512 + h4];
    float4 gg = *(const float4*)&g[1024 + h4];
    float4 go = *(const float4*)&g[1536 + h4];
    float4 cp = *(const float4*)&c0[(size_t)b * Hh + h4];
    float4 c, hh;
    c.x = sigmoid_fast(gf.x) * cp.x + sigmoid_fast(gi.x) * tanhf(gg.x);
    c.y = sigmoid_fast(gf.y) * cp.y + sigmoid_fast(gi.y) * tanhf(gg.y);
    c.z = sigmoid_fast(gf.z) * cp.z + sigmoid_fast(gi.z) * tanhf(gg.z);
    c.w = sigmoid_fast(gf.w) * cp.w + sigmoid_fast(gi.w) * tanhf(gg.w);
    hh.x = sigmoid_fast(go.x) * tanhf(c.x);
    hh.y = sigmoid_fast(go.y) * tanhf(c.y);
    hh.z = sigmoid_fast(go.z) * tanhf(c.z);
    hh.w = sigmoid_fast(go.w) * tanhf(c.w);
    *(float4*)&out[OFF_H + (size_t)b * Hh + h4] = hh;
    *(float4*)&out[OFF_C + (size_t)b * Hh + h4] = c;
}

// ---------------------------------------------------------------------------
// Attention scores (float4 smem loads -> 3 LDS.128 instead of 12 scalar LDS)
// ---------------------------------------------------------------------------
__global__ __launch_bounds__(256) void scores_kernel(
    const float* __restrict__ ef, const float* __restrict__ dec,
    const float* __restrict__ vw, const float* __restrict__ Wc,
    const float* __restrict__ cov, float* __restrict__ scores)
{
    __shared__ __align__(16) float s_dec[H2];
    __shared__ __align__(16) float s_v[H2];
    __shared__ __align__(16) float s_wc[H2];
    int b = blockIdx.y;
    int tid = threadIdx.x;
    for (int i = tid; i < H2; i += 256) {
        s_dec[i] = dec[(size_t)b * H2 + i];
        s_v[i] = vw[i];
        s_wc[i] = Wc[i];
    }
    __syncthreads();

    int warp = tid >> 5, lane = tid & 31;
    int t = blockIdx.x * 8 + warp;
    float cv = cov[(size_t)b * Tt + t];
    const float* p = ef + ((size_t)b * Tt + t) * H2;

    float acc = 0.0f;
#pragma unroll
    for (int i = 0; i < 8; i++) {
        int n = i * 128 + lane * 4;
        float4 e4 = *(const float4*)(p + n);
        float4 d4 = *(const float4*)&s_dec[n];
        float4 w4 = *(const float4*)&s_wc[n];
        float4 v4 = *(const float4*)&s_v[n];
        acc += tanh_fast(e4.x + d4.x + cv * w4.x) * v4.x;
        acc += tanh_fast(e4.y + d4.y + cv * w4.y) * v4.y;
        acc += tanh_fast(e4.z + d4.z + cv * w4.z) * v4.z;
        acc += tanh_fast(e4.w + d4.w + cv * w4.w) * v4.w;
    }
#pragma unroll
    for (int o = 16; o > 0; o >>= 1) acc += __shfl_down_sync(0xffffffffu, acc, o);
    if (lane == 0) scores[(size_t)b * Tt + t] = acc;
}

// ---------------------------------------------------------------------------
// Fused attention: softmax over T (+mask renorm +coverage), half of c_t,
// partial p_gen dot (atomicAdd into g_pgacc). grid (2,128), 512 threads.
// ---------------------------------------------------------------------------
__global__ __launch_bounds__(512) void attn_fused_kernel(
    const float* __restrict__ scores, const float* __restrict__ mask,
    const float* __restrict__ cov, const float* __restrict__ eo,
    const float* __restrict__ x, const float* __restrict__ Wpg,
    float* __restrict__ pgacc, float* __restrict__ out)
{
    __shared__ float red[512];
    __shared__ float sa[Tt];

    int b = blockIdx.y, hx = blockIdx.x, tid = threadIdx.x;

    float s = (tid < Tt) ? scores[(size_t)b * Tt + tid] : -1e30f;
    red[tid] = s; __syncthreads();
    for (int st = 256; st > 0; st >>= 1) {
        if (tid < st) red[tid] = fmaxf(red[tid], red[tid + st]);
        __syncthreads();
    }
    float m = red[0]; __syncthreads();

    float e = (tid < Tt) ? __expf(s - m) : 0.0f;
    red[tid] = e; __syncthreads();
    for (int st = 256; st > 0; st >>= 1) {
        if (tid < st) red[tid] += red[tid + st];
        __syncthreads();
    }
    float S = red[0]; __syncthreads();

    float a = (tid < Tt) ? (e / S) * mask[(size_t)b * Tt + tid] : 0.0f;
    red[tid] = a; __syncthreads();
    for (int st = 256; st > 0; st >>= 1) {
        if (tid < st) red[tid] += red[tid + st];
        __syncthreads();
    }
    float S2 = red[0] + 1e-12f;

    float attn = a / S2;
    if (tid < Tt) {
        sa[tid] = attn;
        if (hx == 0) {
            out[OFF_ATTN + (size_t)b * Tt + tid] = attn;
            out[OFF_COV  + (size_t)b * Tt + tid] = cov[(size_t)b * Tt + tid] + attn;
        }
    }
    __syncthreads();

    int n = hx * 512 + tid;
    const float* p = eo + (size_t)b * Tt * H2 + n;
    float acc = 0.0f;
#pragma unroll 16
    for (int t = 0; t < Tt; t++) acc += sa[t] * p[(size_t)t * H2];
    out[OFF_CT + (size_t)b * H2 + n] = acc;

    float pacc = acc * Wpg[n];
    if (hx == 0) {
        pacc += out[OFF_H + (size_t)b * Hh + tid] * Wpg[1024 + tid];
        if (tid < Ee) pacc += x[(size_t)b * Ee + tid] * Wpg[2048 + tid];
    } else {
        pacc += out[OFF_C + (size_t)b * Hh + tid] * Wpg[1536 + tid];
    }
    red[tid] = pacc; __syncthreads();
    for (int st = 256; st > 0; st >>= 1) {
        if (tid < st) red[tid] += red[tid + st];
        __syncthreads();
    }
    if (tid == 0) atomicAdd(&pgacc[b], red[0]);
}

// ---------------------------------------------------------------------------
// Final: F = expL * pg / S (single pass) + p_gen finalize + pointer scatter
// + scratch re-zero. grid = 128, 1024 threads.
// All threads read gpg/gsums BEFORE thread 0 zeroes them (barrier-ordered).
// ---------------------------------------------------------------------------
__global__ __launch_bounds__(1024) void vsoftmax_scatter_kernel(
    const float* __restrict__ expL, const int* __restrict__ ebev,
    const float* __restrict__ bpg,
    float* __restrict__ gx, float* __restrict__ ggates,
    float* __restrict__ gdec, float* __restrict__ go1,
    float* __restrict__ gpg, float* __restrict__ gsums,
    float* __restrict__ out)
{
    int b = blockIdx.x, tid = threadIdx.x;

    float pgacc_v = gpg[b];
    float S = gsums[b];
    __syncthreads();
    if (tid == 0) {
        gpg[b] = 0.0f;
        gsums[b] = 0.0f;
    }

    float pg = sigmoid_fast(pgacc_v + bpg[0]);
    if (tid == 0) out[OFF_PGEN + b] = pg;

    float scale = pg / S;
    const float4* L4 = (const float4*)(expL + (size_t)b * Vv);
    float4* F4 = (float4*)(out + (size_t)b * Vv);
    for (int j = tid; j < Vv / 4; j += 1024) {
        float4 v = L4[j];
        F4[j] = make_float4(v.x * scale, v.y * scale, v.z * scale, v.w * scale);
    }
    __syncthreads();

    if (tid < Tt) {
        float a = out[OFF_ATTN + (size_t)b * Tt + tid];
        atomicAdd(&out[(size_t)b * Vv + ebev[(size_t)b * Tt + tid]], (1.0f - pg) * a);
    }

    // re-zero split-GEMM accumulators for the next call
    int gi = b * 1024 + tid;
    int gs = 128 * 1024;
    for (int j = gi; j < Bb * Ee; j += gs) gx[j] = 0.0f;
    for (int j = gi; j < Bb * 4 * Hh; j += gs) ggates[j] = 0.0f;
    for (int j = gi; j < Bb * H2; j += gs) gdec[j] = 0.0f;
    for (int j = gi; j < Bb * Hh; j += gs) go1[j] = 0.0f;
}

// ---------------------------------------------------------------------------
// Host launch
// ---------------------------------------------------------------------------
static void launch_small(const float* A1, int lda1, int K1, const float* W1, int ldw1,
                         const float* A2, int lda2, int K2, const float* W2, int ldw2,
                         const int* a2_idx,
                         const float* b1, const float* b2, float* C, int N, int kchunk)
{
    int steps = (K1 + K2) >> 4;
    int ky = (steps + kchunk - 1) / kchunk;
    dim3 grid(N / 128, ky);
    small_gemm_mma<<<grid, 256, SG_SMEM_BYTES>>>(
        A1, lda1, K1, W1, ldw1, A2, lda2, K2, W2, ldw2,
        a2_idx, b1, b2, C, N, kchunk, (ky > 1) ? 1 : 0);
}

extern "C" void kernel_launch(void* const* d_in, const int* in_sizes, int n_in,
                              void* d_out_v, int out_size)
{
    (void)in_sizes; (void)n_in; (void)out_size;
    const int*   y    = (const int*)  d_in[0];
    const float* h0   = (const float*)d_in[1];
    const float* c0   = (const float*)d_in[2];
    const float* ct1  = (const float*)d_in[3];
    const float* eo   = (const float*)d_in[4];
    const float* ef   = (const float*)d_in[5];
    const float* mask = (const float*)d_in[6];
    const int*   ebev = (const int*)  d_in[7];
    const float* cov  = (const float*)d_in[8];
    const float* emb  = (const float*)d_in[9];
    const float* W_c  = (const float*)d_in[10];
    const float* W_dp = (const float*)d_in[11];
    const float* b_dp = (const float*)d_in[12];
    const float* v_w  = (const float*)d_in[13];
    const float* W_xc = (const float*)d_in[14];
    const float* b_xc = (const float*)d_in[15];
    const float* W_ih = (const float*)d_in[16];
    const float* W_hh = (const float*)d_in[17];
    const float* b_ih = (const float*)d_in[18];
    const float* b_hh = (const float*)d_in[19];
    const float* W_pg = (const float*)d_in[20];
    const float* b_pg = (const float*)d_in[21];
    const float* W_o1 = (const float*)d_in[22];
    const float* b_o1 = (const float*)d_in[23];
    const float* W_o2 = (const float*)d_in[24];
    const float* b_o2 = (const float*)d_in[25];
    float* out = (float*)d_out_v;

    float *p_x, *p_gates, *p_dec, *p_scores, *p_o1, *p_logits, *p_pgacc, *p_sums;
    cudaGetSymbolAddress((void**)&p_x,      g_x);
    cudaGetSymbolAddress((void**)&p_gates,  g_gates);
    cudaGetSymbolAddress((void**)&p_dec,    g_decfea);
    cudaGetSymbolAddress((void**)&p_scores, g_scores);
    cudaGetSymbolAddress((void**)&p_o1,     g_o1);
    cudaGetSymbolAddress((void**)&p_logits, g_logits);
    cudaGetSymbolAddress((void**)&p_pgacc,  g_pgacc);
    cudaGetSymbolAddress((void**)&p_sums,   g_sums);

    cudaFuncSetAttribute(vocab_gemm_mma, cudaFuncAttributeMaxDynamicSharedMemorySize,
                         VG_SMEM_BYTES);
    cudaFuncSetAttribute(small_gemm_mma, cudaFuncAttributeMaxDynamicSharedMemorySize,
                         SG_SMEM_BYTES);

    // Accumulators are zero here (module-load init + re-zero in final kernel).

    // 1. x = [c_t_1 | emb[y]] @ W_xc^T + b_xc  (grid (1,72))
    launch_small(ct1, H2, H2, W_xc, 1152,
                 emb, Ee, Ee, W_xc + 1024, 1152, y,
                 b_xc, nullptr, p_x, Ee, 1);

    // 2. gates = x @ W_ih^T + h0 @ W_hh^T + biases  (grid (16,8), nc=5)
    launch_small(p_x, Ee, Ee, W_ih, Ee,
                 h0, Hh, Hh, W_hh, Hh, nullptr,
                 b_ih, b_hh, p_gates, 4 * Hh, 5);

    // 3. LSTM cell
    lstm_kernel<<<(Bb * Hh / 4 + 255) / 256, 256>>>(p_gates, c0, out);

    // 4. dec_fea = [h | c] @ W_dp^T + b_dp  (grid (8,16), nc=4)
    launch_small(out + OFF_H, Hh, Hh, W_dp, H2,
                 out + OFF_C, Hh, Hh, W_dp + 512, H2, nullptr,
                 b_dp, nullptr, p_dec, H2, 4);

    // 5. attention scores
    scores_kernel<<<dim3(Tt / 8, Bb), 256>>>(ef, p_dec, v_w, W_c, cov, p_scores);

    // 6. fused softmax + c_t halves + partial p_gen
    attn_fused_kernel<<<dim3(2, Bb), 512>>>(p_scores, mask, cov, eo, p_x, W_pg,
                                            p_pgacc, out);

    // 7. o1 = [h | c_t] @ W_o1^T + b_o1  (grid (4,32), nc=3)
    launch_small(out + OFF_H, Hh, Hh, W_o1, 3 * Hh,
                 out + OFF_CT, H2, H2, W_o1 + 512, 3 * Hh, nullptr,
                 b_o1, nullptr, p_o1, Hh, 3);

    // 8. exp(logits) + row sums via bf16 MMA GEMM
    vocab_gemm_mma<<<(Vv + 127) / 128, 256, VG_SMEM_BYTES>>>(p_o1, W_o2, b_o2,
                                                             p_logits, p_sums);

    // 9. final: scale expL by pg/S + scatter + re-zero
    vsoftmax_scatter_kernel<<<Bb, 1024>>>(p_logits, ebev, b_pg,
                                          p_x, p_gates, p_dec, p_o1,
                                          p_pgacc, p_sums, out);
}

// round 17
// speedup vs baseline: 1.1851x; 1.0130x over previous
#include <cuda_runtime.h>
#include <math.h>
#include <stdint.h>

// Problem constants
#define Bb 128
#define Tt 400
#define Hh 512
#define H2 1024
#define Ee 128
#define Vv 50000

// Output layout (concatenated reference tuple, row-major each)
#define OFF_FINAL 0L
#define OFF_H     6400000L
#define OFF_C     6465536L
#define OFF_CT    6531072L
#define OFF_ATTN  6662144L
#define OFF_PGEN  6713344L
#define OFF_COV   6713472L

// Scratch (device globals: zero-initialized at module load; re-zeroed by the
// tail of vsoftmax_scatter_kernel so every call starts AND ends zeroed).
__device__ float g_x[Bb * Ee];
__device__ float g_gates[Bb * 4 * Hh];
__device__ float g_decfea[Bb * H2];
__device__ float g_scores[Bb * Tt];
__device__ float g_o1[Bb * Hh];
__device__ float g_pgacc[Bb];
__device__ float g_sums[Bb];
__device__ float g_logits[(size_t)Bb * Vv];   // holds exp(logits)

__device__ __forceinline__ float tanh_fast(float x) {
    float y;
    asm("tanh.approx.f32 %0, %1;" : "=f"(y) : "f"(x));
    return y;
}
__device__ __forceinline__ float sigmoid_fast(float x) {
    return 1.0f / (1.0f + __expf(-x));
}
__device__ __forceinline__ uint32_t cvt_bf2(float2 v) {
    uint32_t r;
    asm("cvt.rn.bf16x2.f32 %0, %1, %2;" : "=r"(r) : "f"(v.y), "f"(v.x));
    return r;
}
__device__ __forceinline__ uint32_t smem_u32(const void* p) {
    return (uint32_t)__cvta_generic_to_shared(p);
}

// ---------------------------------------------------------------------------
// Small GEMM on tensor cores (tf32 m16n8k8, raw fp32 bits):
// C[128, N] (+)= [A1 | A2] @ [W1 | W2]^T + bias1 + bias2
// CTA tile 128x128, BK=16, 4-stage cp.async pipeline, K-split + atomicAdd.
// ---------------------------------------------------------------------------
#define SG_LDS 20
#define SG_STAGEF (128 * SG_LDS)
#define SG_STAGEB (SG_STAGEF * 4)
#define SG_STAGES 4
#define SG_SMEM_BYTES (SG_STAGES * SG_STAGEB * 2)   // 81920

__global__ __launch_bounds__(256) void small_gemm_mma(
    const float* __restrict__ A1, int lda1, int K1,
    const float* __restrict__ W1, int ldw1,
    const float* __restrict__ A2, int lda2, int K2,
    const float* __restrict__ W2, int ldw2,
    const int* __restrict__ a2_idx,
    const float* __restrict__ bias1, const float* __restrict__ bias2,
    float* __restrict__ C, int N, int kchunk, int split)
{
    extern __shared__ __align__(16) float sgsm[];
    float* As = sgsm;
    float* Ws = sgsm + SG_STAGES * SG_STAGEF;

    int tid = threadIdx.x;
    int lane = tid & 31;
    int wid = tid >> 5;
    int wm = (wid & 1) * 64;
    int wn = (wid >> 1) * 32;
    int bn0 = blockIdx.x * 128;
    int grp = lane >> 2;
    int qid = lane & 3;

    uint32_t sA = smem_u32(As);
    uint32_t sW = smem_u32(Ws);

    int steps_total = (K1 + K2) >> 4;
    int s0 = blockIdx.y * kchunk;
    int s1 = min(s0 + kchunk, steps_total);
    if (s0 >= steps_total) return;
    int nc = s1 - s0;

    auto prefetch = [&](int s, int stage) {
        int kk = s << 4;
        const float* Ap; int lda; int ko;
        const float* Wp; int ldw;
        bool ind = false;
        if (kk < K1) { Ap = A1; lda = lda1; ko = kk;      Wp = W1; ldw = ldw1; }
        else         { Ap = A2; lda = lda2; ko = kk - K1; Wp = W2; ldw = ldw2;
                       ind = (a2_idx != nullptr); }
#pragma unroll
        for (int i = 0; i < 2; i++) {
            int slot = i * 256 + tid;
            int row = slot >> 2;
            int c4 = (slot & 3) << 2;
            uint32_t soff = (uint32_t)(stage * SG_STAGEB + (row * SG_LDS + c4) * 4);
            size_t aoff = ind ? (size_t)a2_idx[row] * lda : (size_t)row * lda;
            asm volatile("cp.async.cg.shared.global [%0], [%1], 16;"
                         :: "r"(sA + soff), "l"(Ap + aoff + ko + c4) : "memory");
            asm volatile("cp.async.cg.shared.global [%0], [%1], 16;"
                         :: "r"(sW + soff), "l"(Wp + (size_t)(bn0 + row) * ldw + ko + c4)
                         : "memory");
        }
        asm volatile("cp.async.commit_group;" ::: "memory");
    };

    float acc[4][4][4];
#pragma unroll
    for (int i = 0; i < 4; i++)
#pragma unroll
        for (int j = 0; j < 4; j++)
#pragma unroll
            for (int r = 0; r < 4; r++) acc[i][j][r] = 0.0f;

    int committed = 0;
    for (; committed < nc && committed < 3; committed++)
        prefetch(s0 + committed, committed & 3);

    for (int s = 0; s < nc; s++) {
        if (committed < nc) { prefetch(s0 + committed, committed & 3); committed++; }
        int allow = committed - s - 1;
        if (allow <= 0)      asm volatile("cp.async.wait_group 0;" ::: "memory");
        else if (allow == 1) asm volatile("cp.async.wait_group 1;" ::: "memory");
        else if (allow == 2) asm volatile("cp.async.wait_group 2;" ::: "memory");
        else                 asm volatile("cp.async.wait_group 3;" ::: "memory");
        __syncthreads();

        const float* as = As + (s & 3) * SG_STAGEF;
        const float* ws = Ws + (s & 3) * SG_STAGEF;

#pragma unroll
        for (int k8 = 0; k8 < 2; k8++) {
            int kk = k8 * 8;
            uint32_t af[4][4];
#pragma unroll
            for (int t = 0; t < 4; t++) {
                int r0 = wm + t * 16 + grp;
                af[t][0] = __float_as_uint(as[r0 * SG_LDS + kk + qid]);
                af[t][1] = __float_as_uint(as[(r0 + 8) * SG_LDS + kk + qid]);
                af[t][2] = __float_as_uint(as[r0 * SG_LDS + kk + qid + 4]);
                af[t][3] = __float_as_uint(as[(r0 + 8) * SG_LDS + kk + qid + 4]);
            }
            uint32_t bf[4][2];
#pragma unroll
            for (int t = 0; t < 4; t++) {
                int n0 = wn + t * 8 + grp;
                bf[t][0] = __float_as_uint(ws[n0 * SG_LDS + kk + qid]);
                bf[t][1] = __float_as_uint(ws[n0 * SG_LDS + kk + qid + 4]);
            }
#pragma unroll
            for (int i = 0; i < 4; i++)
#pragma unroll
                for (int j = 0; j < 4; j++) {
                    asm volatile(
                        "mma.sync.aligned.m16n8k8.row.col.f32.tf32.tf32.f32 "
                        "{%0,%1,%2,%3}, {%4,%5,%6,%7}, {%8,%9}, {%0,%1,%2,%3};"
                        : "+f"(acc[i][j][0]), "+f"(acc[i][j][1]),
                          "+f"(acc[i][j][2]), "+f"(acc[i][j][3])
                        : "r"(af[i][0]), "r"(af[i][1]), "r"(af[i][2]), "r"(af[i][3]),
                          "r"(bf[j][0]), "r"(bf[j][1]));
                }
        }
        __syncthreads();
    }

    bool addb = (blockIdx.y == 0);
#pragma unroll
    for (int i = 0; i < 4; i++) {
        int m0 = wm + i * 16 + grp;
#pragma unroll
        for (int j = 0; j < 4; j++) {
            int n = bn0 + wn + j * 8 + 2 * qid;
            float b0 = 0.0f, b1 = 0.0f;
            if (addb) {
                if (bias1) { b0 += bias1[n]; b1 += bias1[n + 1]; }
                if (bias2) { b0 += bias2[n]; b1 += bias2[n + 1]; }
            }
            if (split) {
                atomicAdd(&C[(size_t)m0 * N + n],           acc[i][j][0] + b0);
                atomicAdd(&C[(size_t)m0 * N + n + 1],       acc[i][j][1] + b1);
                atomicAdd(&C[(size_t)(m0 + 8) * N + n],     acc[i][j][2] + b0);
                atomicAdd(&C[(size_t)(m0 + 8) * N + n + 1], acc[i][j][3] + b1);
            } else {
                C[(size_t)m0 * N + n]           = acc[i][j][0] + b0;
                C[(size_t)m0 * N + n + 1]       = acc[i][j][1] + b1;
                C[(size_t)(m0 + 8) * N + n]     = acc[i][j][2] + b0;
                C[(size_t)(m0 + 8) * N + n + 1] = acc[i][j][3] + b1;
            }
        }
    }
}

// ---------------------------------------------------------------------------
// Vocab GEMM: bf16 m16n8k16 MMA + 4-stage cp.async fp32 pipeline.
// Writes EL = exp(o1 @ W_o2^T + b_o2) and accumulates per-row sums into
// gsums[128] (softmax is shift-invariant; logits are O(0.1), no overflow).
// ---------------------------------------------------------------------------
#define VG_LDS 24
#define VG_STAGEF (128 * VG_LDS)
#define VG_STAGEB (VG_STAGEF * 4)
#define VG_STAGES 4
#define VG_SMEM_BYTES (VG_STAGES * VG_STAGEB * 2)   // 98304

__device__ __forceinline__ void vg_prefetch(
    int s, int stage, const float* __restrict__ A, const float* __restrict__ W,
    int bn0, uint32_t sA, uint32_t sW)
{
    int ck = s * 16;
    int tid = threadIdx.x;
#pragma unroll
    for (int i = 0; i < 2; i++) {
        int slot = i * 256 + tid;
        int row = slot >> 2;
        int c4 = (slot & 3) << 2;
        uint32_t soff = (uint32_t)(stage * VG_STAGEB + (row * VG_LDS + c4) * 4);
        asm volatile("cp.async.cg.shared.global [%0], [%1], 16;"
                     :: "r"(sA + soff), "l"(A + row * 512 + ck + c4) : "memory");
        int nrow = bn0 + row;
        if (nrow < Vv)
            asm volatile("cp.async.cg.shared.global [%0], [%1], 16;"
                         :: "r"(sW + soff), "l"(W + (size_t)nrow * 512 + ck + c4) : "memory");
    }
    asm volatile("cp.async.commit_group;" ::: "memory");
}

__global__ __launch_bounds__(256) void vocab_gemm_mma(
    const float* __restrict__ A, const float* __restrict__ W,
    const float* __restrict__ bias, float* __restrict__ EL,
    float* __restrict__ gsums)
{
    extern __shared__ __align__(16) float vgsm[];
    float* As = vgsm;
    float* Ws = vgsm + VG_STAGES * VG_STAGEF;

    int tid = threadIdx.x;
    int lane = tid & 31;
    int wid = tid >> 5;
    int wm = (wid & 1) * 64;
    int wn = (wid >> 1) * 32;
    int bn0 = blockIdx.x * 128;

    int grp = lane >> 2;
    int qid = lane & 3;

    uint32_t sA = smem_u32(As);
    uint32_t sW = smem_u32(Ws);

    if (bn0 + 128 > Vv) {
#pragma unroll
        for (int st = 0; st < VG_STAGES; st++)
            for (int slot = tid; slot < 512; slot += 256) {
                int row = slot >> 2;
                int c4 = (slot & 3) << 2;
                if (bn0 + row >= Vv)
                    *(float4*)&Ws[st * VG_STAGEF + row * VG_LDS + c4] =
                        make_float4(0.f, 0.f, 0.f, 0.f);
            }
        __syncthreads();
    }

    float acc[4][4][4];
#pragma unroll
    for (int i = 0; i < 4; i++)
#pragma unroll
        for (int j = 0; j < 4; j++)
#pragma unroll
            for (int r = 0; r < 4; r++) acc[i][j][r] = 0.0f;

    vg_prefetch(0, 0, A, W, bn0, sA, sW);
    vg_prefetch(1, 1, A, W, bn0, sA, sW);
    vg_prefetch(2, 2, A, W, bn0, sA, sW);

    for (int s = 0; s < 32; s++) {
        int stage = s & 3;
        if (s < 29) {
            vg_prefetch(s + 3, (s + 3) & 3, A, W, bn0, sA, sW);
            asm volatile("cp.async.wait_group 3;" ::: "memory");
        } else if (s == 29) {
            asm volatile("cp.async.wait_group 2;" ::: "memory");
        } else if (s == 30) {
            asm volatile("cp.async.wait_group 1;" ::: "memory");
        } else {
            asm volatile("cp.async.wait_group 0;" ::: "memory");
        }
        __syncthreads();

        const float* as = As + stage * VG_STAGEF;
        const float* ws = Ws + stage * VG_STAGEF;

        uint32_t af[4][4];
#pragma unroll
        for (int t = 0; t < 4; t++) {
            int r0 = wm + t * 16 + grp;
            const float* b0 = as + r0 * VG_LDS;
            const float* b1 = as + (r0 + 8) * VG_LDS;
            af[t][0] = cvt_bf2(*(const float2*)(b0 + 2 * qid));
            af[t][1] = cvt_bf2(*(const float2*)(b1 + 2 * qid));
            af[t][2] = cvt_bf2(*(const float2*)(b0 + 8 + 2 * qid));
            af[t][3] = cvt_bf2(*(const float2*)(b1 + 8 + 2 * qid));
        }
        uint32_t bf[4][2];
#pragma unroll
        for (int t = 0; t < 4; t++) {
            int n0 = wn + t * 8 + grp;
            const float* b = ws + n0 * VG_LDS;
            bf[t][0] = cvt_bf2(*(const float2*)(b + 2 * qid));
            bf[t][1] = cvt_bf2(*(const float2*)(b + 8 + 2 * qid));
        }
#pragma unroll
        for (int i = 0; i < 4; i++)
#pragma unroll
            for (int j = 0; j < 4; j++) {
                asm volatile(
                    "mma.sync.aligned.m16n8k16.row.col.f32.bf16.bf16.f32 "
                    "{%0,%1,%2,%3}, {%4,%5,%6,%7}, {%8,%9}, {%0,%1,%2,%3};"
                    : "+f"(acc[i][j][0]), "+f"(acc[i][j][1]),
                      "+f"(acc[i][j][2]), "+f"(acc[i][j][3])
                    : "r"(af[i][0]), "r"(af[i][1]), "r"(af[i][2]), "r"(af[i][3]),
                      "r"(bf[j][0]), "r"(bf[j][1]));
            }
        __syncthreads();
    }

    // Epilogue: exp(logit) store + per-row sum reduction.
    float* rowsums = vgsm;
    if (tid < 128) rowsums[tid] = 0.0f;
    __syncthreads();

#pragma unroll
    for (int i = 0; i < 4; i++) {
        int m0 = wm + i * 16 + grp;
        float rsA = 0.0f, rsB = 0.0f;
#pragma unroll
        for (int j = 0; j < 4; j++) {
            int n = bn0 + wn + j * 8 + 2 * qid;
            if (n < Vv) {
                float2 b2 = *(const float2*)&bias[n];
                float e0 = __expf(acc[i][j][0] + b2.x);
                float e1 = __expf(acc[i][j][1] + b2.y);
                float e2 = __expf(acc[i][j][2] + b2.x);
                float e3 = __expf(acc[i][j][3] + b2.y);
                *(float2*)&EL[(size_t)m0 * Vv + n]       = make_float2(e0, e1);
                *(float2*)&EL[(size_t)(m0 + 8) * Vv + n] = make_float2(e2, e3);
                rsA += e0 + e1;
                rsB += e2 + e3;
            }
        }
        rsA += __shfl_down_sync(0xffffffffu, rsA, 2);
        rsA += __shfl_down_sync(0xffffffffu, rsA, 1);
        rsB += __shfl_down_sync(0xffffffffu, rsB, 2);
        rsB += __shfl_down_sync(0xffffffffu, rsB, 1);
        if (qid == 0) {
            atomicAdd(&rowsums[m0], rsA);
            atomicAdd(&rowsums[m0 + 8], rsB);
        }
    }
    __syncthreads();
    if (tid < 128) atomicAdd(&gsums[tid], rowsums[tid]);
}

// ---------------------------------------------------------------------------
// LSTM elementwise (float4 vectorized)
// ---------------------------------------------------------------------------
__global__ void lstm_kernel(const float* __restrict__ gates, const float* __restrict__ c0,
                            float* __restrict__ out) {
    int q = blockIdx.x * blockDim.x + threadIdx.x;
    if (q >= Bb * Hh / 4) return;
    int b = q >> 7;
    int h4 = (q & 127) << 2;
    const float* g = gates + (size_t)b * 4 * Hh;
    float4 gi = *(const float4*)&g[h4];
    float4 gf = *(const float4*)&g[512 + h4];
    float4 gg = *(const float4*)&g[1024 + h4];
    float4 go = *(const float4*)&g[1536 + h4];
    float4 cp = *(const float4*)&c0[(size_t)b * Hh + h4];
    float4 c, hh;
    c.x = sigmoid_fast(gf.x) * cp.x + sigmoid_fast(gi.x) * tanhf(gg.x);
    c.y = sigmoid_fast(gf.y) * cp.y + sigmoid_fast(gi.y) * tanhf(gg.y);
    c.z = sigmoid_fast(gf.z) * cp.z + sigmoid_fast(gi.z) * tanhf(gg.z);
    c.w = sigmoid_fast(gf.w) * cp.w + sigmoid_fast(gi.w) * tanhf(gg.w);
    hh.x = sigmoid_fast(go.x) * tanhf(c.x);
    hh.y = sigmoid_fast(go.y) * tanhf(c.y);
    hh.z = sigmoid_fast(go.z) * tanhf(c.z);
    hh.w = sigmoid_fast(go.w) * tanhf(c.w);
    *(float4*)&out[OFF_H + (size_t)b * Hh + h4] = hh;
    *(float4*)&out[OFF_C + (size_t)b * Hh + h4] = c;
}

// ---------------------------------------------------------------------------
// Attention scores: 32 t-rows per block (4 per warp, interleaved loads).
// grid (13, 128), 256 threads. smem fill amortized 4x vs 8-t version.
// ---------------------------------------------------------------------------
__global__ __launch_bounds__(256) void scores_kernel(
    const float* __restrict__ ef, const float* __restrict__ dec,
    const float* __restrict__ vw, const float* __restrict__ Wc,
    const float* __restrict__ cov, float* __restrict__ scores)
{
    __shared__ __align__(16) float s_dec[H2];
    __shared__ __align__(16) float s_v[H2];
    __shared__ __align__(16) float s_wc[H2];
    int b = blockIdx.y;
    int tid = threadIdx.x;
    for (int i = tid; i < H2 / 4; i += 256) {
        *(float4*)&s_dec[i * 4] = *(const float4*)&dec[(size_t)b * H2 + i * 4];
        *(float4*)&s_v[i * 4]   = *(const float4*)&vw[i * 4];
        *(float4*)&s_wc[i * 4]  = *(const float4*)&Wc[i * 4];
    }
    __syncthreads();

    int warp = tid >> 5, lane = tid & 31;
    int tb = blockIdx.x * 32;

    const float* p[4];
    float cv[4];
    bool ok[4];
    float acc[4];
#pragma unroll
    for (int r = 0; r < 4; r++) {
        int t = tb + r * 8 + warp;
        ok[r] = (t < Tt);
        int tc = ok[r] ? t : (Tt - 1);
        cv[r] = cov[(size_t)b * Tt + tc];
        p[r] = ef + ((size_t)b * Tt + tc) * H2;
        acc[r] = 0.0f;
    }

#pragma unroll
    for (int i = 0; i < 8; i++) {
        int n = i * 128 + lane * 4;
        float4 d4 = *(const float4*)&s_dec[n];
        float4 w4 = *(const float4*)&s_wc[n];
        float4 v4 = *(const float4*)&s_v[n];
        float4 e[4];
#pragma unroll
        for (int r = 0; r < 4; r++) e[r] = *(const float4*)(p[r] + n);
#pragma unroll
        for (int r = 0; r < 4; r++) {
            acc[r] += tanh_fast(e[r].x + d4.x + cv[r] * w4.x) * v4.x;
            acc[r] += tanh_fast(e[r].y + d4.y + cv[r] * w4.y) * v4.y;
            acc[r] += tanh_fast(e[r].z + d4.z + cv[r] * w4.z) * v4.z;
            acc[r] += tanh_fast(e[r].w + d4.w + cv[r] * w4.w) * v4.w;
        }
    }
#pragma unroll
    for (int r = 0; r < 4; r++) {
#pragma unroll
        for (int o = 16; o > 0; o >>= 1)
            acc[r] += __shfl_down_sync(0xffffffffu, acc[r], o);
        if (lane == 0 && ok[r])
            scores[(size_t)b * Tt + tb + r * 8 + warp] = acc[r];
    }
}

// ---------------------------------------------------------------------------
// Fused attention: softmax over T (+mask renorm +coverage), half of c_t,
// partial p_gen dot (atomicAdd into g_pgacc). grid (2,128), 512 threads.
// ---------------------------------------------------------------------------
__global__ __launch_bounds__(512) void attn_fused_kernel(
    const float* __restrict__ scores, const float* __restrict__ mask,
    const float* __restrict__ cov, const float* __restrict__ eo,
    const float* __restrict__ x, const float* __restrict__ Wpg,
    float* __restrict__ pgacc, float* __restrict__ out)
{
    __shared__ float red[512];
    __shared__ float sa[Tt];

    int b = blockIdx.y, hx = blockIdx.x, tid = threadIdx.x;

    float s = (tid < Tt) ? scores[(size_t)b * Tt + tid] : -1e30f;
    red[tid] = s; __syncthreads();
    for (int st = 256; st > 0; st >>= 1) {
        if (tid < st) red[tid] = fmaxf(red[tid], red[tid + st]);
        __syncthreads();
    }
    float m = red[0]; __syncthreads();

    float e = (tid < Tt) ? __expf(s - m) : 0.0f;
    red[tid] = e; __syncthreads();
    for (int st = 256; st > 0; st >>= 1) {
        if (tid < st) red[tid] += red[tid + st];
        __syncthreads();
    }
    float S = red[0]; __syncthreads();

    float a = (tid < Tt) ? (e / S) * mask[(size_t)b * Tt + tid] : 0.0f;
    red[tid] = a; __syncthreads();
    for (int st = 256; st > 0; st >>= 1) {
        if (tid < st) red[tid] += red[tid + st];
        __syncthreads();
    }
    float S2 = red[0] + 1e-12f;

    float attn = a / S2;
    if (tid < Tt) {
        sa[tid] = attn;
        if (hx == 0) {
            out[OFF_ATTN + (size_t)b * Tt + tid] = attn;
            out[OFF_COV  + (size_t)b * Tt + tid] = cov[(size_t)b * Tt + tid] + attn;
        }
    }
    __syncthreads();

    int n = hx * 512 + tid;
    const float* p = eo + (size_t)b * Tt * H2 + n;
    float acc = 0.0f;
#pragma unroll 16
    for (int t = 0; t < Tt; t++) acc += sa[t] * p[(size_t)t * H2];
    out[OFF_CT + (size_t)b * H2 + n] = acc;

    float pacc = acc * Wpg[n];
    if (hx == 0) {
        pacc += out[OFF_H + (size_t)b * Hh + tid] * Wpg[1024 + tid];
        if (tid < Ee) pacc += x[(size_t)b * Ee + tid] * Wpg[2048 + tid];
    } else {
        pacc += out[OFF_C + (size_t)b * Hh + tid] * Wpg[1536 + tid];
    }
    red[tid] = pacc; __syncthreads();
    for (int st = 256; st > 0; st >>= 1) {
        if (tid < st) red[tid] += red[tid + st];
        __syncthreads();
    }
    if (tid == 0) atomicAdd(&pgacc[b], red[0]);
}

// ---------------------------------------------------------------------------
// Final: F = expL * pg / S (single pass) + p_gen finalize + pointer scatter
// + scratch re-zero. grid = 128, 1024 threads.
// All threads read gpg/gsums BEFORE thread 0 zeroes them (barrier-ordered).
// ---------------------------------------------------------------------------
__global__ __launch_bounds__(1024) void vsoftmax_scatter_kernel(
    const float* __restrict__ expL, const int* __restrict__ ebev,
    const float* __restrict__ bpg,
    float* __restrict__ gx, float* __restrict__ ggates,
    float* __restrict__ gdec, float* __restrict__ go1,
    float* __restrict__ gpg, float* __restrict__ gsums,
    float* __restrict__ out)
{
    int b = blockIdx.x, tid = threadIdx.x;

    float pgacc_v = gpg[b];
    float S = gsums[b];
    __syncthreads();
    if (tid == 0) {
        gpg[b] = 0.0f;
        gsums[b] = 0.0f;
    }

    float pg = sigmoid_fast(pgacc_v + bpg[0]);
    if (tid == 0) out[OFF_PGEN + b] = pg;

    float scale = pg / S;
    const float4* L4 = (const float4*)(expL + (size_t)b * Vv);
    float4* F4 = (float4*)(out + (size_t)b * Vv);
    for (int j = tid; j < Vv / 4; j += 1024) {
        float4 v = L4[j];
        F4[j] = make_float4(v.x * scale, v.y * scale, v.z * scale, v.w * scale);
    }
    __syncthreads();

    if (tid < Tt) {
        float a = out[OFF_ATTN + (size_t)b * Tt + tid];
        atomicAdd(&out[(size_t)b * Vv + ebev[(size_t)b * Tt + tid]], (1.0f - pg) * a);
    }

    // re-zero split-GEMM accumulators for the next call
    int gi = b * 1024 + tid;
    int gs = 128 * 1024;
    for (int j = gi; j < Bb * Ee; j += gs) gx[j] = 0.0f;
    for (int j = gi; j < Bb * 4 * Hh; j += gs) ggates[j] = 0.0f;
    for (int j = gi; j < Bb * H2; j += gs) gdec[j] = 0.0f;
    for (int j = gi; j < Bb * Hh; j += gs) go1[j] = 0.0f;
}

// ---------------------------------------------------------------------------
// Host launch
// ---------------------------------------------------------------------------
static void launch_small(const float* A1, int lda1, int K1, const float* W1, int ldw1,
                         const float* A2, int lda2, int K2, const float* W2, int ldw2,
                         const int* a2_idx,
                         const float* b1, const float* b2, float* C, int N, int kchunk)
{
    int steps = (K1 + K2) >> 4;
    int ky = (steps + kchunk - 1) / kchunk;
    dim3 grid(N / 128, ky);
    small_gemm_mma<<<grid, 256, SG_SMEM_BYTES>>>(
        A1, lda1, K1, W1, ldw1, A2, lda2, K2, W2, ldw2,
        a2_idx, b1, b2, C, N, kchunk, (ky > 1) ? 1 : 0);
}

extern "C" void kernel_launch(void* const* d_in, const int* in_sizes, int n_in,
                              void* d_out_v, int out_size)
{
    (void)in_sizes; (void)n_in; (void)out_size;
    const int*   y    = (const int*)  d_in[0];
    const float* h0   = (const float*)d_in[1];
    const float* c0   = (const float*)d_in[2];
    const float* ct1  = (const float*)d_in[3];
    const float* eo   = (const float*)d_in[4];
    const float* ef   = (const float*)d_in[5];
    const float* mask = (const float*)d_in[6];
    const int*   ebev = (const int*)  d_in[7];
    const float* cov  = (const float*)d_in[8];
    const float* emb  = (const float*)d_in[9];
    const float* W_c  = (const float*)d_in[10];
    const float* W_dp = (const float*)d_in[11];
    const float* b_dp = (const float*)d_in[12];
    const float* v_w  = (const float*)d_in[13];
    const float* W_xc = (const float*)d_in[14];
    const float* b_xc = (const float*)d_in[15];
    const float* W_ih = (const float*)d_in[16];
    const float* W_hh = (const float*)d_in[17];
    const float* b_ih = (const float*)d_in[18];
    const float* b_hh = (const float*)d_in[19];
    const float* W_pg = (const float*)d_in[20];
    const float* b_pg = (const float*)d_in[21];
    const float* W_o1 = (const float*)d_in[22];
    const float* b_o1 = (const float*)d_in[23];
    const float* W_o2 = (const float*)d_in[24];
    const float* b_o2 = (const float*)d_in[25];
    float* out = (float*)d_out_v;

    float *p_x, *p_gates, *p_dec, *p_scores, *p_o1, *p_logits, *p_pgacc, *p_sums;
    cudaGetSymbolAddress((void**)&p_x,      g_x);
    cudaGetSymbolAddress((void**)&p_gates,  g_gates);
    cudaGetSymbolAddress((void**)&p_dec,    g_decfea);
    cudaGetSymbolAddress((void**)&p_scores, g_scores);
    cudaGetSymbolAddress((void**)&p_o1,     g_o1);
    cudaGetSymbolAddress((void**)&p_logits, g_logits);
    cudaGetSymbolAddress((void**)&p_pgacc,  g_pgacc);
    cudaGetSymbolAddress((void**)&p_sums,   g_sums);

    cudaFuncSetAttribute(vocab_gemm_mma, cudaFuncAttributeMaxDynamicSharedMemorySize,
                         VG_SMEM_BYTES);
    cudaFuncSetAttribute(small_gemm_mma, cudaFuncAttributeMaxDynamicSharedMemorySize,
                         SG_SMEM_BYTES);

    // Accumulators are zero here (module-load init + re-zero in final kernel).

    // 1. x = [c_t_1 | emb[y]] @ W_xc^T + b_xc  (grid (1,72))
    launch_small(ct1, H2, H2, W_xc, 1152,
                 emb, Ee, Ee, W_xc + 1024, 1152, y,
                 b_xc, nullptr, p_x, Ee, 1);

    // 2. gates = x @ W_ih^T + h0 @ W_hh^T + biases  (grid (16,8), nc=5)
    launch_small(p_x, Ee, Ee, W_ih, Ee,
                 h0, Hh, Hh, W_hh, Hh, nullptr,
                 b_ih, b_hh, p_gates, 4 * Hh, 5);

    // 3. LSTM cell
    lstm_kernel<<<(Bb * Hh / 4 + 255) / 256, 256>>>(p_gates, c0, out);

    // 4. dec_fea = [h | c] @ W_dp^T + b_dp  (grid (8,16), nc=4)
    launch_small(out + OFF_H, Hh, Hh, W_dp, H2,
                 out + OFF_C, Hh, Hh, W_dp + 512, H2, nullptr,
                 b_dp, nullptr, p_dec, H2, 4);

    // 5. attention scores (32 t per block)
    scores_kernel<<<dim3((Tt + 31) / 32, Bb), 256>>>(ef, p_dec, v_w, W_c, cov, p_scores);

    // 6. fused softmax + c_t halves + partial p_gen
    attn_fused_kernel<<<dim3(2, Bb), 512>>>(p_scores, mask, cov, eo, p_x, W_pg,
                                            p_pgacc, out);

    // 7. o1 = [h | c_t] @ W_o1^T + b_o1  (grid (4,32), nc=3)
    launch_small(out + OFF_H, Hh, Hh, W_o1, 3 * Hh,
                 out + OFF_CT, H2, H2, W_o1 + 512, 3 * Hh, nullptr,
                 b_o1, nullptr, p_o1, Hh, 3);

    // 8. exp(logits) + row sums via bf16 MMA GEMM
    vocab_gemm_mma<<<(Vv + 127) / 128, 256, VG_SMEM_BYTES>>>(p_o1, W_o2, b_o2,
                                                             p_logits, p_sums);

    // 9. final: scale expL by pg/S + scatter + re-zero
    vsoftmax_scatter_kernel<<<Bb, 1024>>>(p_logits, ebev, b_pg,
                                          p_x, p_gates, p_dec, p_o1,
                                          p_pgacc, p_sums, out);
}